// round 7
// baseline (speedup 1.0000x reference)
#include <cuda_runtime.h>
#include <cstdint>

#define BATCH 32
#define NTOK  1024
#define DIM   256
#define KNN   8
#define EPSV  1e-8f

#define BM 128
#define BN 128
#define BK 16

typedef unsigned long long u64;

// ---- scratch (static __device__ globals; no allocation allowed) ----
__device__ float g_tn[(size_t)BATCH * NTOK * DIM];          // 32 MB
__device__ float g_sim[(size_t)BATCH * NTOK * NTOK];        // 134 MB
__device__ int   g_topk[BATCH * NTOK * KNN];                // 1 MB

// ---- packed fp32x2 helpers (FFMA2: 2x fp32 FMA per issue on sm_103a) ----
__device__ __forceinline__ u64 pk2(float a) {
    u64 r; asm("mov.b64 %0, {%1, %1};" : "=l"(r) : "f"(a)); return r;
}
__device__ __forceinline__ void fma2(u64& d, u64 a, u64 b) {
    asm("fma.rn.f32x2 %0, %1, %2, %0;" : "+l"(d) : "l"(a), "l"(b));
}
__device__ __forceinline__ void unpk2(float& lo, float& hi, u64 v) {
    asm("mov.b64 {%0, %1}, %2;" : "=f"(lo), "=f"(hi) : "l"(v));
}

// ============================================================
// K1: row-normalize tokens  (one warp per row of 256 floats)
// ============================================================
__global__ void k_normalize(const float* __restrict__ x) {
    int warp = (blockIdx.x * blockDim.x + threadIdx.x) >> 5;
    int lane = threadIdx.x & 31;
    if (warp >= BATCH * NTOK) return;
    const float4* row = (const float4*)(x + (size_t)warp * DIM);
    float4 v0 = row[lane * 2 + 0];
    float4 v1 = row[lane * 2 + 1];
    float s = v0.x * v0.x + v0.y * v0.y + v0.z * v0.z + v0.w * v0.w
            + v1.x * v1.x + v1.y * v1.y + v1.z * v1.z + v1.w * v1.w;
    #pragma unroll
    for (int o = 16; o; o >>= 1) s += __shfl_xor_sync(0xffffffffu, s, o);
    float inv = 1.0f / (sqrtf(s) + EPSV);
    float4* out = (float4*)(g_tn + (size_t)warp * DIM);
    v0.x *= inv; v0.y *= inv; v0.z *= inv; v0.w *= inv;
    v1.x *= inv; v1.y *= inv; v1.z *= inv; v1.w *= inv;
    out[lane * 2 + 0] = v0;
    out[lane * 2 + 1] = v1;
}

// ============================================================
// K2: sim[b] = tn[b] * tn[b]^T, SYMMETRIC (36 tile-pairs).
//   - A stored DUPLICATED as {a,a} pairs -> 4 front-batched
//     LDS.128 per kk (broadcast, conflict-free), ZERO inner MOVs.
//   - B split cols [tx*4,+4) & [64+tx*4,+4): conflict-free LDS.64.
//   - Next k0's LDG.128s issued before the compute burst
//     (register prefetch) so L2 latency hides under FFMA2 work.
//   Inner loop: 4 LDS.128 + 4 LDS.64 + 32 FFMA2 = 40 issues/kk.
// ============================================================
__global__ __launch_bounds__(256, 2) void k_gemm() {
    __shared__ float As2[BK][2 * BM];   // 16 KB, duplicated pairs
    __shared__ float Bs[BK][BN];        //  8 KB

    // decode triangular tile pair: rowTile ti <= colTile tj
    int t = blockIdx.x;
    int ti = 0;
    while (t >= 8 - ti) { t -= 8 - ti; ti++; }
    const int tj = ti + t;

    const int b       = blockIdx.z;
    const int rowBase = ti * BM;
    const int colBase = tj * BN;
    const float* __restrict__ A = g_tn + (size_t)b * NTOK * DIM;

    const int tid = threadIdx.x;
    const int tx  = tid & 15;      // col groups: tx*4 and 64+tx*4
    const int ty  = tid >> 4;      // rows ty*8 .. +7

    // global load mapping: thread -> (row = tid/2, k-sub = (tid&1)*8)
    const int lr = tid >> 1;
    const int lk = (tid & 1) * 8;

    u64 acc[8][4];
    #pragma unroll
    for (int i = 0; i < 8; i++)
        #pragma unroll
        for (int j = 0; j < 4; j++) acc[i][j] = 0ull;

    const float* ap = A + (size_t)(rowBase + lr) * DIM + lk;
    const float* bp = A + (size_t)(colBase + lr) * DIM + lk;

    // prologue: prefetch k0 = 0
    float4 a0 = *(const float4*)(ap);
    float4 a1 = *(const float4*)(ap + 4);
    float4 b0 = *(const float4*)(bp);
    float4 b1 = *(const float4*)(bp + 4);

    for (int k0 = 0; k0 < DIM; k0 += BK) {
        __syncthreads();   // prev compute done before overwriting smem
        // A duplicated: STS.64 of {a,a}
        *(u64*)&As2[lk + 0][2 * lr] = pk2(a0.x);
        *(u64*)&As2[lk + 1][2 * lr] = pk2(a0.y);
        *(u64*)&As2[lk + 2][2 * lr] = pk2(a0.z);
        *(u64*)&As2[lk + 3][2 * lr] = pk2(a0.w);
        *(u64*)&As2[lk + 4][2 * lr] = pk2(a1.x);
        *(u64*)&As2[lk + 5][2 * lr] = pk2(a1.y);
        *(u64*)&As2[lk + 6][2 * lr] = pk2(a1.z);
        *(u64*)&As2[lk + 7][2 * lr] = pk2(a1.w);
        Bs[lk + 0][lr] = b0.x; Bs[lk + 1][lr] = b0.y;
        Bs[lk + 2][lr] = b0.z; Bs[lk + 3][lr] = b0.w;
        Bs[lk + 4][lr] = b1.x; Bs[lk + 5][lr] = b1.y;
        Bs[lk + 6][lr] = b1.z; Bs[lk + 7][lr] = b1.w;
        __syncthreads();

        // prefetch next k0 (issued before compute; latency hidden)
        if (k0 + BK < DIM) {
            a0 = *(const float4*)(ap + k0 + BK);
            a1 = *(const float4*)(ap + k0 + BK + 4);
            b0 = *(const float4*)(bp + k0 + BK);
            b1 = *(const float4*)(bp + k0 + BK + 4);
        }

        #pragma unroll
        for (int kk = 0; kk < BK; kk++) {
            ulonglong2 A01 = *(const ulonglong2*)&As2[kk][ty * 16 + 0];
            ulonglong2 A23 = *(const ulonglong2*)&As2[kk][ty * 16 + 4];
            ulonglong2 A45 = *(const ulonglong2*)&As2[kk][ty * 16 + 8];
            ulonglong2 A67 = *(const ulonglong2*)&As2[kk][ty * 16 + 12];
            u64 bq0 = *(const u64*)&Bs[kk][tx * 4 + 0];
            u64 bq1 = *(const u64*)&Bs[kk][tx * 4 + 2];
            u64 bq2 = *(const u64*)&Bs[kk][64 + tx * 4 + 0];
            u64 bq3 = *(const u64*)&Bs[kk][64 + tx * 4 + 2];
            fma2(acc[0][0],A01.x,bq0); fma2(acc[0][1],A01.x,bq1); fma2(acc[0][2],A01.x,bq2); fma2(acc[0][3],A01.x,bq3);
            fma2(acc[1][0],A01.y,bq0); fma2(acc[1][1],A01.y,bq1); fma2(acc[1][2],A01.y,bq2); fma2(acc[1][3],A01.y,bq3);
            fma2(acc[2][0],A23.x,bq0); fma2(acc[2][1],A23.x,bq1); fma2(acc[2][2],A23.x,bq2); fma2(acc[2][3],A23.x,bq3);
            fma2(acc[3][0],A23.y,bq0); fma2(acc[3][1],A23.y,bq1); fma2(acc[3][2],A23.y,bq2); fma2(acc[3][3],A23.y,bq3);
            fma2(acc[4][0],A45.x,bq0); fma2(acc[4][1],A45.x,bq1); fma2(acc[4][2],A45.x,bq2); fma2(acc[4][3],A45.x,bq3);
            fma2(acc[5][0],A45.y,bq0); fma2(acc[5][1],A45.y,bq1); fma2(acc[5][2],A45.y,bq2); fma2(acc[5][3],A45.y,bq3);
            fma2(acc[6][0],A67.x,bq0); fma2(acc[6][1],A67.x,bq1); fma2(acc[6][2],A67.x,bq2); fma2(acc[6][3],A67.x,bq3);
            fma2(acc[7][0],A67.y,bq0); fma2(acc[7][1],A67.y,bq1); fma2(acc[7][2],A67.y,bq2); fma2(acc[7][3],A67.y,bq3);
        }
    }

    float* C = g_sim + (size_t)b * NTOK * NTOK;

    // unpack 8x8 micro-tile: v[i][0..3] -> cols tx*4.., v[i][4..7] -> cols 64+tx*4..
    float v[8][8];
    #pragma unroll
    for (int i = 0; i < 8; i++) {
        unpk2(v[i][0], v[i][1], acc[i][0]);
        unpk2(v[i][2], v[i][3], acc[i][1]);
        unpk2(v[i][4], v[i][5], acc[i][2]);
        unpk2(v[i][6], v[i][7], acc[i][3]);
    }

    // normal store
    #pragma unroll
    for (int i = 0; i < 8; i++) {
        float* dst = C + (size_t)(rowBase + ty * 8 + i) * NTOK + colBase;
        *(float4*)(dst + tx * 4)      = make_float4(v[i][0], v[i][1], v[i][2], v[i][3]);
        *(float4*)(dst + 64 + tx * 4) = make_float4(v[i][4], v[i][5], v[i][6], v[i][7]);
    }

    // mirror store for off-diagonal tiles: C[col][row block]
    if (ti != tj) {
        #pragma unroll
        for (int j = 0; j < 8; j++) {
            int cj = (j < 4) ? (tx * 4 + j) : (64 + tx * 4 + (j - 4));
            float* dst = C + (size_t)(colBase + cj) * NTOK + rowBase + ty * 8;
            *(float4*)(dst)     = make_float4(v[0][j], v[1][j], v[2][j], v[3][j]);
            *(float4*)(dst + 4) = make_float4(v[4][j], v[5][j], v[6][j], v[7][j]);
        }
    }
}

// ============================================================
// K3: top-8 per row (one warp / row): lane-local sorted-8,
//     then 8-round tournament merge across lanes.
// ============================================================
__global__ void k_topk() {
    int gr   = (blockIdx.x * blockDim.x + threadIdx.x) >> 5;
    int lane = threadIdx.x & 31;
    if (gr >= BATCH * NTOK) return;
    int n = gr & (NTOK - 1);
    const float* __restrict__ row = g_sim + (size_t)gr * NTOK;

    float val[KNN];
    int   idx[KNN];
    #pragma unroll
    for (int i = 0; i < KNN; i++) { val[i] = -3.4e38f; idx[i] = -1; }

    #pragma unroll 4
    for (int i = 0; i < NTOK / 32; i++) {
        int j = lane + i * 32;
        float v = row[j];
        if (j == n) v = -3.4e38f;          // mask self
        if (v > val[KNN - 1]) {
            val[KNN - 1] = v; idx[KNN - 1] = j;
            #pragma unroll
            for (int p = KNN - 1; p > 0; --p) {
                if (val[p] > val[p - 1]) {
                    float tv = val[p]; val[p] = val[p - 1]; val[p - 1] = tv;
                    int   ti = idx[p]; idx[p] = idx[p - 1]; idx[p - 1] = ti;
                }
            }
        }
    }

    int ptr = 0;
    #pragma unroll
    for (int t = 0; t < KNN; t++) {
        float hv = (ptr < KNN) ? val[ptr] : -3.4e38f;
        int   hj = (ptr < KNN) ? idx[ptr] : -1;
        float bv = hv; int bl = lane;
        #pragma unroll
        for (int off = 16; off; off >>= 1) {
            float ov = __shfl_down_sync(0xffffffffu, bv, off);
            int   ol = __shfl_down_sync(0xffffffffu, bl, off);
            if (ov > bv) { bv = ov; bl = ol; }
        }
        bl = __shfl_sync(0xffffffffu, bl, 0);          // broadcast winner lane
        int bj = __shfl_sync(0xffffffffu, hj, bl);     // winner's index
        if (lane == 0) g_topk[gr * KNN + t] = bj;
        if (lane == bl) ptr++;
    }
}

// ============================================================
// K4: zero output
// ============================================================
__global__ void k_zero(float4* __restrict__ out, int n4) {
    int i      = blockIdx.x * blockDim.x + threadIdx.x;
    int stride = gridDim.x * blockDim.x;
    for (; i < n4; i += stride) out[i] = make_float4(0.f, 0.f, 0.f, 0.f);
}

// ============================================================
// K5: mutual-kNN edge scatter (one thread per (row, t))
// ============================================================
__global__ void k_mutual(float* __restrict__ out) {
    int e = blockIdx.x * blockDim.x + threadIdx.x;
    if (e >= BATCH * NTOK * KNN) return;
    int gr = e >> 3;            // global row
    int t  = e & 7;
    int b  = gr >> 10;
    int n  = gr & (NTOK - 1);
    int j  = g_topk[gr * KNN + t];
    const int* tj = g_topk + ((b << 10) + j) * KNN;
    bool mutual = false;
    #pragma unroll
    for (int s = 0; s < KNN; s++) mutual |= (tj[s] == n);
    if (mutual)
        out[((size_t)b << 20) + ((size_t)n << 10) + (size_t)j] = 1.0f;
}

// ============================================================
extern "C" void kernel_launch(void* const* d_in, const int* in_sizes, int n_in,
                              void* d_out, int out_size) {
    const float* tokens = (const float*)d_in[0];
    float* out = (float*)d_out;

    // K1: 8 rows per 256-thread block
    k_normalize<<<BATCH * NTOK / 8, 256>>>(tokens);

    // K2: 36 triangular tile-pairs per batch
    dim3 gg(36, 1, BATCH);
    k_gemm<<<gg, 256>>>();

    // K3: 8 warps per block, one row each
    k_topk<<<BATCH * NTOK / 8, 256>>>();

    // K4: zero 134 MB output
    k_zero<<<2048, 256>>>((float4*)out, BATCH * NTOK * NTOK / 4);

    // K5: mutual edges
    k_mutual<<<(BATCH * NTOK * KNN + 255) / 256, 256>>>(out);
}

// round 9
// speedup vs baseline: 1.0206x; 1.0206x over previous
#include <cuda_runtime.h>
#include <cstdint>

#define BATCH 32
#define NTOK  1024
#define DIM   256
#define KNN   8
#define EPSV  1e-8f

#define BM 128
#define BN 128
#define BK 16

typedef unsigned long long u64;

// ---- scratch (static __device__ globals; no allocation allowed) ----
__device__ float g_tn[(size_t)BATCH * NTOK * DIM];          // 32 MB
__device__ float g_sim[(size_t)BATCH * NTOK * NTOK];        // 134 MB
__device__ int   g_topk[BATCH * NTOK * KNN];                // 1 MB

// ---- packed fp32x2 helpers (FFMA2: 2x fp32 FMA per issue on sm_103a) ----
__device__ __forceinline__ u64 pk2(float a) {
    u64 r; asm("mov.b64 %0, {%1, %1};" : "=l"(r) : "f"(a)); return r;
}
__device__ __forceinline__ void fma2(u64& d, u64 a, u64 b) {
    asm("fma.rn.f32x2 %0, %1, %2, %0;" : "+l"(d) : "l"(a), "l"(b));
}
__device__ __forceinline__ void unpk2(float& lo, float& hi, u64 v) {
    asm("mov.b64 {%0, %1}, %2;" : "=f"(lo), "=f"(hi) : "l"(v));
}

// ============================================================
// K1: row-normalize tokens  (one warp per row of 256 floats)
// ============================================================
__global__ void k_normalize(const float* __restrict__ x) {
    int warp = (blockIdx.x * blockDim.x + threadIdx.x) >> 5;
    int lane = threadIdx.x & 31;
    if (warp >= BATCH * NTOK) return;
    const float4* row = (const float4*)(x + (size_t)warp * DIM);
    float4 v0 = row[lane * 2 + 0];
    float4 v1 = row[lane * 2 + 1];
    float s = v0.x * v0.x + v0.y * v0.y + v0.z * v0.z + v0.w * v0.w
            + v1.x * v1.x + v1.y * v1.y + v1.z * v1.z + v1.w * v1.w;
    #pragma unroll
    for (int o = 16; o; o >>= 1) s += __shfl_xor_sync(0xffffffffu, s, o);
    float inv = 1.0f / (sqrtf(s) + EPSV);
    float4* out = (float4*)(g_tn + (size_t)warp * DIM);
    v0.x *= inv; v0.y *= inv; v0.z *= inv; v0.w *= inv;
    v1.x *= inv; v1.y *= inv; v1.z *= inv; v1.w *= inv;
    out[lane * 2 + 0] = v0;
    out[lane * 2 + 1] = v1;
}

// ============================================================
// K2: sim[b] = tn[b] * tn[b]^T, SYMMETRIC (36 tile-pairs),
//     DOUBLE-BUFFERED: LDG for tile t+1 before compute of t,
//     STS to alternate buffer after, single sync per k0.
//     Inner body = R6 proven schedule (unchanged).
// ============================================================
__global__ __launch_bounds__(256, 2) void k_gemm() {
    __shared__ float As[2][BK][BM];   // 2 x 8 KB
    __shared__ float Bs[2][BK][BN];   // 2 x 8 KB

    // decode triangular tile pair: rowTile ti <= colTile tj
    int t = blockIdx.x;
    int ti = 0;
    while (t >= 8 - ti) { t -= 8 - ti; ti++; }
    const int tj = ti + t;

    const int b       = blockIdx.z;
    const int rowBase = ti * BM;
    const int colBase = tj * BN;
    const float* __restrict__ A = g_tn + (size_t)b * NTOK * DIM;

    const int tid = threadIdx.x;
    const int tx  = tid & 15;      // col groups: tx*4 and 64+tx*4
    const int ty  = tid >> 4;      // rows ty*8 .. +7

    // global load mapping: thread -> (row = tid/2, k-sub = (tid&1)*8)
    const int lr = tid >> 1;
    const int lk = (tid & 1) * 8;

    u64 acc[8][4];
    #pragma unroll
    for (int i = 0; i < 8; i++)
        #pragma unroll
        for (int j = 0; j < 4; j++) acc[i][j] = 0ull;

    const float* ap = A + (size_t)(rowBase + lr) * DIM + lk;
    const float* bp = A + (size_t)(colBase + lr) * DIM + lk;

    // prologue: load tile 0 and fill buffer 0
    float4 a0 = *(const float4*)(ap);
    float4 a1 = *(const float4*)(ap + 4);
    float4 b0 = *(const float4*)(bp);
    float4 b1 = *(const float4*)(bp + 4);
    As[0][lk + 0][lr] = a0.x; As[0][lk + 1][lr] = a0.y;
    As[0][lk + 2][lr] = a0.z; As[0][lk + 3][lr] = a0.w;
    As[0][lk + 4][lr] = a1.x; As[0][lk + 5][lr] = a1.y;
    As[0][lk + 6][lr] = a1.z; As[0][lk + 7][lr] = a1.w;
    Bs[0][lk + 0][lr] = b0.x; Bs[0][lk + 1][lr] = b0.y;
    Bs[0][lk + 2][lr] = b0.z; Bs[0][lk + 3][lr] = b0.w;
    Bs[0][lk + 4][lr] = b1.x; Bs[0][lk + 5][lr] = b1.y;
    Bs[0][lk + 6][lr] = b1.z; Bs[0][lk + 7][lr] = b1.w;
    __syncthreads();

    int p = 0;
    for (int k0 = 0; k0 < DIM; k0 += BK) {
        const bool hasNext = (k0 + BK < DIM);
        // issue next tile's global loads BEFORE the compute burst
        if (hasNext) {
            a0 = *(const float4*)(ap + k0 + BK);
            a1 = *(const float4*)(ap + k0 + BK + 4);
            b0 = *(const float4*)(bp + k0 + BK);
            b1 = *(const float4*)(bp + k0 + BK + 4);
        }

        #pragma unroll
        for (int kk = 0; kk < BK; kk++) {
            float4 av0 = *(const float4*)&As[p][kk][ty * 8];
            float4 av1 = *(const float4*)&As[p][kk][ty * 8 + 4];
            u64 bq0 = *(const u64*)&Bs[p][kk][tx * 4 + 0];
            u64 bq1 = *(const u64*)&Bs[p][kk][tx * 4 + 2];
            u64 bq2 = *(const u64*)&Bs[p][kk][64 + tx * 4 + 0];
            u64 bq3 = *(const u64*)&Bs[p][kk][64 + tx * 4 + 2];
            u64 q;
            q = pk2(av0.x); fma2(acc[0][0],q,bq0); fma2(acc[0][1],q,bq1); fma2(acc[0][2],q,bq2); fma2(acc[0][3],q,bq3);
            q = pk2(av0.y); fma2(acc[1][0],q,bq0); fma2(acc[1][1],q,bq1); fma2(acc[1][2],q,bq2); fma2(acc[1][3],q,bq3);
            q = pk2(av0.z); fma2(acc[2][0],q,bq0); fma2(acc[2][1],q,bq1); fma2(acc[2][2],q,bq2); fma2(acc[2][3],q,bq3);
            q = pk2(av0.w); fma2(acc[3][0],q,bq0); fma2(acc[3][1],q,bq1); fma2(acc[3][2],q,bq2); fma2(acc[3][3],q,bq3);
            q = pk2(av1.x); fma2(acc[4][0],q,bq0); fma2(acc[4][1],q,bq1); fma2(acc[4][2],q,bq2); fma2(acc[4][3],q,bq3);
            q = pk2(av1.y); fma2(acc[5][0],q,bq0); fma2(acc[5][1],q,bq1); fma2(acc[5][2],q,bq2); fma2(acc[5][3],q,bq3);
            q = pk2(av1.z); fma2(acc[6][0],q,bq0); fma2(acc[6][1],q,bq1); fma2(acc[6][2],q,bq2); fma2(acc[6][3],q,bq3);
            q = pk2(av1.w); fma2(acc[7][0],q,bq0); fma2(acc[7][1],q,bq1); fma2(acc[7][2],q,bq2); fma2(acc[7][3],q,bq3);
        }

        // fill the other buffer; one sync covers "reads of p done"
        // and "writes of 1-p visible"
        if (hasNext) {
            int q = p ^ 1;
            As[q][lk + 0][lr] = a0.x; As[q][lk + 1][lr] = a0.y;
            As[q][lk + 2][lr] = a0.z; As[q][lk + 3][lr] = a0.w;
            As[q][lk + 4][lr] = a1.x; As[q][lk + 5][lr] = a1.y;
            As[q][lk + 6][lr] = a1.z; As[q][lk + 7][lr] = a1.w;
            Bs[q][lk + 0][lr] = b0.x; Bs[q][lk + 1][lr] = b0.y;
            Bs[q][lk + 2][lr] = b0.z; Bs[q][lk + 3][lr] = b0.w;
            Bs[q][lk + 4][lr] = b1.x; Bs[q][lk + 5][lr] = b1.y;
            Bs[q][lk + 6][lr] = b1.z; Bs[q][lk + 7][lr] = b1.w;
            __syncthreads();
            p = q;
        }
    }

    float* C = g_sim + (size_t)b * NTOK * NTOK;

    // unpack 8x8 micro-tile: v[i][0..3] -> cols tx*4.., v[i][4..7] -> cols 64+tx*4..
    float v[8][8];
    #pragma unroll
    for (int i = 0; i < 8; i++) {
        unpk2(v[i][0], v[i][1], acc[i][0]);
        unpk2(v[i][2], v[i][3], acc[i][1]);
        unpk2(v[i][4], v[i][5], acc[i][2]);
        unpk2(v[i][6], v[i][7], acc[i][3]);
    }

    // normal store
    #pragma unroll
    for (int i = 0; i < 8; i++) {
        float* dst = C + (size_t)(rowBase + ty * 8 + i) * NTOK + colBase;
        *(float4*)(dst + tx * 4)      = make_float4(v[i][0], v[i][1], v[i][2], v[i][3]);
        *(float4*)(dst + 64 + tx * 4) = make_float4(v[i][4], v[i][5], v[i][6], v[i][7]);
    }

    // mirror store for off-diagonal tiles: C[col][row block]
    if (ti != tj) {
        #pragma unroll
        for (int j = 0; j < 8; j++) {
            int cj = (j < 4) ? (tx * 4 + j) : (64 + tx * 4 + (j - 4));
            float* dst = C + (size_t)(colBase + cj) * NTOK + rowBase + ty * 8;
            *(float4*)(dst)     = make_float4(v[0][j], v[1][j], v[2][j], v[3][j]);
            *(float4*)(dst + 4) = make_float4(v[4][j], v[5][j], v[6][j], v[7][j]);
        }
    }
}

// ============================================================
// K3: top-8 per row (one warp / row): lane-local sorted-8,
//     then 8-round tournament merge across lanes.
// ============================================================
__global__ void k_topk() {
    int gr   = (blockIdx.x * blockDim.x + threadIdx.x) >> 5;
    int lane = threadIdx.x & 31;
    if (gr >= BATCH * NTOK) return;
    int n = gr & (NTOK - 1);
    const float* __restrict__ row = g_sim + (size_t)gr * NTOK;

    float val[KNN];
    int   idx[KNN];
    #pragma unroll
    for (int i = 0; i < KNN; i++) { val[i] = -3.4e38f; idx[i] = -1; }

    #pragma unroll 4
    for (int i = 0; i < NTOK / 32; i++) {
        int j = lane + i * 32;
        float v = row[j];
        if (j == n) v = -3.4e38f;          // mask self
        if (v > val[KNN - 1]) {
            val[KNN - 1] = v; idx[KNN - 1] = j;
            #pragma unroll
            for (int p = KNN - 1; p > 0; --p) {
                if (val[p] > val[p - 1]) {
                    float tv = val[p]; val[p] = val[p - 1]; val[p - 1] = tv;
                    int   ti = idx[p]; idx[p] = idx[p - 1]; idx[p - 1] = ti;
                }
            }
        }
    }

    int ptr = 0;
    #pragma unroll
    for (int t = 0; t < KNN; t++) {
        float hv = (ptr < KNN) ? val[ptr] : -3.4e38f;
        int   hj = (ptr < KNN) ? idx[ptr] : -1;
        float bv = hv; int bl = lane;
        #pragma unroll
        for (int off = 16; off; off >>= 1) {
            float ov = __shfl_down_sync(0xffffffffu, bv, off);
            int   ol = __shfl_down_sync(0xffffffffu, bl, off);
            if (ov > bv) { bv = ov; bl = ol; }
        }
        bl = __shfl_sync(0xffffffffu, bl, 0);          // broadcast winner lane
        int bj = __shfl_sync(0xffffffffu, hj, bl);     // winner's index
        if (lane == 0) g_topk[gr * KNN + t] = bj;
        if (lane == bl) ptr++;
    }
}

// ============================================================
// K4: zero output
// ============================================================
__global__ void k_zero(float4* __restrict__ out, int n4) {
    int i      = blockIdx.x * blockDim.x + threadIdx.x;
    int stride = gridDim.x * blockDim.x;
    for (; i < n4; i += stride) out[i] = make_float4(0.f, 0.f, 0.f, 0.f);
}

// ============================================================
// K5: mutual-kNN edge scatter (one thread per (row, t))
// ============================================================
__global__ void k_mutual(float* __restrict__ out) {
    int e = blockIdx.x * blockDim.x + threadIdx.x;
    if (e >= BATCH * NTOK * KNN) return;
    int gr = e >> 3;            // global row
    int t  = e & 7;
    int b  = gr >> 10;
    int n  = gr & (NTOK - 1);
    int j  = g_topk[gr * KNN + t];
    const int* tj = g_topk + ((b << 10) + j) * KNN;
    bool mutual = false;
    #pragma unroll
    for (int s = 0; s < KNN; s++) mutual |= (tj[s] == n);
    if (mutual)
        out[((size_t)b << 20) + ((size_t)n << 10) + (size_t)j] = 1.0f;
}

// ============================================================
extern "C" void kernel_launch(void* const* d_in, const int* in_sizes, int n_in,
                              void* d_out, int out_size) {
    const float* tokens = (const float*)d_in[0];
    float* out = (float*)d_out;

    // K1: 8 rows per 256-thread block
    k_normalize<<<BATCH * NTOK / 8, 256>>>(tokens);

    // K2: 36 triangular tile-pairs per batch
    dim3 gg(36, 1, BATCH);
    k_gemm<<<gg, 256>>>();

    // K3: 8 warps per block, one row each
    k_topk<<<BATCH * NTOK / 8, 256>>>();

    // K4: zero 134 MB output
    k_zero<<<2048, 256>>>((float4*)out, BATCH * NTOK * NTOK / 4);

    // K5: mutual edges
    k_mutual<<<(BATCH * NTOK * KNN + 255) / 256, 256>>>(out);
}

// round 10
// speedup vs baseline: 1.0865x; 1.0646x over previous
#include <cuda_runtime.h>
#include <cuda_bf16.h>
#include <cstdint>

#define BATCH 32
#define NTOK  1024
#define DIM   256
#define KNN   8
#define NCAND 16
#define EPSV  1e-8f

typedef unsigned long long u64;

// ---- scratch (static __device__ globals; no allocation allowed) ----
__device__ float         g_tn [(size_t)BATCH * NTOK * DIM];   // 32 MB fp32 (exact rescore)
__device__ __nv_bfloat16 g_tnh[(size_t)BATCH * NTOK * DIM];   // 16 MB bf16 (MMA filter)
__device__ float         g_sim[(size_t)BATCH * NTOK * NTOK];  // 134 MB approx sim
__device__ int           g_cand[BATCH * NTOK * NCAND];        // 2 MB candidates
__device__ int           g_topk[BATCH * NTOK * KNN];          // 1 MB exact top-8

// ============================================================
// K1: row-normalize; write fp32 AND bf16 copies
// ============================================================
__global__ void k_normalize(const float* __restrict__ x) {
    int warp = (blockIdx.x * blockDim.x + threadIdx.x) >> 5;
    int lane = threadIdx.x & 31;
    if (warp >= BATCH * NTOK) return;
    const float4* row = (const float4*)(x + (size_t)warp * DIM);
    float4 v0 = row[lane * 2 + 0];
    float4 v1 = row[lane * 2 + 1];
    float s = v0.x * v0.x + v0.y * v0.y + v0.z * v0.z + v0.w * v0.w
            + v1.x * v1.x + v1.y * v1.y + v1.z * v1.z + v1.w * v1.w;
    #pragma unroll
    for (int o = 16; o; o >>= 1) s += __shfl_xor_sync(0xffffffffu, s, o);
    float inv = 1.0f / (sqrtf(s) + EPSV);
    v0.x *= inv; v0.y *= inv; v0.z *= inv; v0.w *= inv;
    v1.x *= inv; v1.y *= inv; v1.z *= inv; v1.w *= inv;
    float4* out = (float4*)(g_tn + (size_t)warp * DIM);
    out[lane * 2 + 0] = v0;
    out[lane * 2 + 1] = v1;
    // bf16 copy (packed pairs, one STG.128 per lane)
    __nv_bfloat162 h0 = __floats2bfloat162_rn(v0.x, v0.y);
    __nv_bfloat162 h1 = __floats2bfloat162_rn(v0.z, v0.w);
    __nv_bfloat162 h2 = __floats2bfloat162_rn(v1.x, v1.y);
    __nv_bfloat162 h3 = __floats2bfloat162_rn(v1.z, v1.w);
    uint4 pk;
    pk.x = *(uint32_t*)&h0; pk.y = *(uint32_t*)&h1;
    pk.z = *(uint32_t*)&h2; pk.w = *(uint32_t*)&h3;
    *(uint4*)(g_tnh + (size_t)warp * DIM + lane * 8) = pk;
}

// ============================================================
// K2: approx sim via bf16 mma.sync (m16n8k16), fp32 accum.
//     128x128 block tile, 8 warps of 32x64, BK=32 stages.
//     smem rows padded to 40 bf16 (80B) -> conflict-free LDS.32.
// ============================================================
__global__ __launch_bounds__(256) void k_gemm_bf16() {
    __shared__ __nv_bfloat16 As[128][40];
    __shared__ __nv_bfloat16 Bs[128][40];

    const int b       = blockIdx.z;
    const int rowBase = blockIdx.y * 128;
    const int colBase = blockIdx.x * 128;
    const __nv_bfloat16* __restrict__ T = g_tnh + (size_t)b * NTOK * DIM;

    const int tid  = threadIdx.x;
    const int wid  = tid >> 5;
    const int lane = tid & 31;
    const int wm = (wid & 3) * 32;   // warp M offset
    const int wn = (wid >> 2) * 64;  // warp N offset
    const int g  = lane >> 2;        // 0..7
    const int c  = lane & 3;         // 0..3

    // fill mapping: thread -> (row = tid/2, 16-bf16 chunk = (tid&1)*16)
    const int fr = tid >> 1;
    const int fk = (tid & 1) * 16;

    float cf[2][8][4];
    #pragma unroll
    for (int mt = 0; mt < 2; mt++)
        #pragma unroll
        for (int nt = 0; nt < 8; nt++)
            #pragma unroll
            for (int e = 0; e < 4; e++) cf[mt][nt][e] = 0.f;

    for (int k0 = 0; k0 < DIM; k0 += 32) {
        __syncthreads();
        {
            const uint4* gA = (const uint4*)(T + (size_t)(rowBase + fr) * DIM + k0 + fk);
            const uint4* gB = (const uint4*)(T + (size_t)(colBase + fr) * DIM + k0 + fk);
            uint4 a0 = gA[0], a1 = gA[1];
            uint4 b0 = gB[0], b1 = gB[1];
            *(uint4*)&As[fr][fk + 0] = a0;
            *(uint4*)&As[fr][fk + 8] = a1;
            *(uint4*)&Bs[fr][fk + 0] = b0;
            *(uint4*)&Bs[fr][fk + 8] = b1;
        }
        __syncthreads();

        #pragma unroll
        for (int ks = 0; ks < 32; ks += 16) {
            // A fragments: 2 m-tiles
            uint32_t a[2][4];
            #pragma unroll
            for (int mt = 0; mt < 2; mt++) {
                int r = wm + mt * 16 + g;
                a[mt][0] = *(const uint32_t*)&As[r    ][ks + 2 * c    ];
                a[mt][1] = *(const uint32_t*)&As[r + 8][ks + 2 * c    ];
                a[mt][2] = *(const uint32_t*)&As[r    ][ks + 2 * c + 8];
                a[mt][3] = *(const uint32_t*)&As[r + 8][ks + 2 * c + 8];
            }
            // B fragments: 8 n-tiles
            uint32_t bb[8][2];
            #pragma unroll
            for (int nt = 0; nt < 8; nt++) {
                int n = wn + nt * 8 + g;
                bb[nt][0] = *(const uint32_t*)&Bs[n][ks + 2 * c    ];
                bb[nt][1] = *(const uint32_t*)&Bs[n][ks + 2 * c + 8];
            }
            #pragma unroll
            for (int mt = 0; mt < 2; mt++)
                #pragma unroll
                for (int nt = 0; nt < 8; nt++) {
                    asm volatile(
                        "mma.sync.aligned.m16n8k16.row.col.f32.bf16.bf16.f32 "
                        "{%0,%1,%2,%3}, {%4,%5,%6,%7}, {%8,%9}, {%0,%1,%2,%3};"
                        : "+f"(cf[mt][nt][0]), "+f"(cf[mt][nt][1]),
                          "+f"(cf[mt][nt][2]), "+f"(cf[mt][nt][3])
                        : "r"(a[mt][0]), "r"(a[mt][1]), "r"(a[mt][2]), "r"(a[mt][3]),
                          "r"(bb[nt][0]), "r"(bb[nt][1]));
                }
        }
    }

    float* C = g_sim + (size_t)b * NTOK * NTOK;
    #pragma unroll
    for (int mt = 0; mt < 2; mt++) {
        #pragma unroll
        for (int nt = 0; nt < 8; nt++) {
            int r0 = rowBase + wm + mt * 16 + g;
            int cc = colBase + wn + nt * 8 + 2 * c;
            *(float2*)(C + (size_t)r0 * NTOK + cc)       = make_float2(cf[mt][nt][0], cf[mt][nt][1]);
            *(float2*)(C + (size_t)(r0 + 8) * NTOK + cc) = make_float2(cf[mt][nt][2], cf[mt][nt][3]);
        }
    }
}

// ============================================================
// K3: top-16 CANDIDATES per row (one warp/row):
//     lane-local sorted-8 + 16-round tournament.
// ============================================================
__global__ void k_topk16() {
    int gr   = (blockIdx.x * blockDim.x + threadIdx.x) >> 5;
    int lane = threadIdx.x & 31;
    if (gr >= BATCH * NTOK) return;
    int n = gr & (NTOK - 1);
    const float* __restrict__ row = g_sim + (size_t)gr * NTOK;

    float val[KNN];
    int   idx[KNN];
    #pragma unroll
    for (int i = 0; i < KNN; i++) { val[i] = -3.4e38f; idx[i] = -1; }

    #pragma unroll 4
    for (int i = 0; i < NTOK / 32; i++) {
        int j = lane + i * 32;
        float v = row[j];
        if (j == n) v = -3.4e38f;          // mask self
        if (v > val[KNN - 1]) {
            val[KNN - 1] = v; idx[KNN - 1] = j;
            #pragma unroll
            for (int p = KNN - 1; p > 0; --p) {
                if (val[p] > val[p - 1]) {
                    float tv = val[p]; val[p] = val[p - 1]; val[p - 1] = tv;
                    int   ti = idx[p]; idx[p] = idx[p - 1]; idx[p - 1] = ti;
                }
            }
        }
    }

    int ptr = 0;
    #pragma unroll
    for (int t = 0; t < NCAND; t++) {
        float hv = (ptr < KNN) ? val[ptr] : -3.4e38f;
        int   hj = (ptr < KNN) ? idx[ptr] : -1;
        float bv = hv; int bl = lane;
        #pragma unroll
        for (int off = 16; off; off >>= 1) {
            float ov = __shfl_down_sync(0xffffffffu, bv, off);
            int   ol = __shfl_down_sync(0xffffffffu, bl, off);
            if (ov > bv) { bv = ov; bl = ol; }
        }
        bl = __shfl_sync(0xffffffffu, bl, 0);
        int bj = __shfl_sync(0xffffffffu, hj, bl);
        if (lane == 0) g_cand[gr * NCAND + t] = bj;
        if (lane == bl) ptr++;
    }
}

// ============================================================
// K4: exact fp32 rescore of 16 candidates -> true top-8 set.
//     One warp per row; candidate rows are L1/L2 resident.
// ============================================================
__global__ void k_rescore() {
    int gr   = (blockIdx.x * blockDim.x + threadIdx.x) >> 5;
    int lane = threadIdx.x & 31;
    if (gr >= BATCH * NTOK) return;
    int b = gr >> 10;
    const float* __restrict__ base = g_tn + ((size_t)(b) << 10) * DIM;
    const float* __restrict__ own  = base + (size_t)(gr & (NTOK - 1)) * DIM;

    float4 o0 = ((const float4*)own)[lane * 2 + 0];
    float4 o1 = ((const float4*)own)[lane * 2 + 1];

    float myscore = -3.4e38f;
    int   myidx   = -1;

    #pragma unroll
    for (int t = 0; t < NCAND; t++) {
        int cj = g_cand[gr * NCAND + t];
        const float* cv = base + (size_t)cj * DIM;
        float4 c0 = ((const float4*)cv)[lane * 2 + 0];
        float4 c1 = ((const float4*)cv)[lane * 2 + 1];
        float p = o0.x * c0.x + o0.y * c0.y + o0.z * c0.z + o0.w * c0.w
                + o1.x * c1.x + o1.y * c1.y + o1.z * c1.z + o1.w * c1.w;
        #pragma unroll
        for (int off = 16; off; off >>= 1) p += __shfl_xor_sync(0xffffffffu, p, off);
        if (lane == t) { myscore = p; myidx = cj; }
    }

    // rank myscore among the 16 (lanes 0..15); ties broken by lane id
    int rank = 0;
    #pragma unroll
    for (int j = 0; j < NCAND; j++) {
        float vj = __shfl_sync(0xffffffffu, myscore, j);
        if (j != lane)
            rank += (vj > myscore) || (vj == myscore && j < lane);
    }
    if (lane < NCAND && rank < KNN)
        g_topk[gr * KNN + rank] = myidx;
}

// ============================================================
// K5: zero output
// ============================================================
__global__ void k_zero(float4* __restrict__ out, int n4) {
    int i      = blockIdx.x * blockDim.x + threadIdx.x;
    int stride = gridDim.x * blockDim.x;
    for (; i < n4; i += stride) out[i] = make_float4(0.f, 0.f, 0.f, 0.f);
}

// ============================================================
// K6: mutual-kNN edge scatter (one thread per (row, t))
// ============================================================
__global__ void k_mutual(float* __restrict__ out) {
    int e = blockIdx.x * blockDim.x + threadIdx.x;
    if (e >= BATCH * NTOK * KNN) return;
    int gr = e >> 3;            // global row
    int t  = e & 7;
    int b  = gr >> 10;
    int n  = gr & (NTOK - 1);
    int j  = g_topk[gr * KNN + t];
    const int* tj = g_topk + ((b << 10) + j) * KNN;
    bool mutual = false;
    #pragma unroll
    for (int s = 0; s < KNN; s++) mutual |= (tj[s] == n);
    if (mutual)
        out[((size_t)b << 20) + ((size_t)n << 10) + (size_t)j] = 1.0f;
}

// ============================================================
extern "C" void kernel_launch(void* const* d_in, const int* in_sizes, int n_in,
                              void* d_out, int out_size) {
    const float* tokens = (const float*)d_in[0];
    float* out = (float*)d_out;

    // K1: 8 rows per 256-thread block
    k_normalize<<<BATCH * NTOK / 8, 256>>>(tokens);

    // K2: bf16 MMA sim, full 8x8 tiles per batch
    dim3 gg(8, 8, BATCH);
    k_gemm_bf16<<<gg, 256>>>();

    // K3: candidate top-16, one warp per row
    k_topk16<<<BATCH * NTOK / 8, 256>>>();

    // K4: exact rescore, one warp per row
    k_rescore<<<BATCH * NTOK / 8, 256>>>();

    // K5: zero 134 MB output
    k_zero<<<2048, 256>>>((float4*)out, BATCH * NTOK * NTOK / 4);

    // K6: mutual edges
    k_mutual<<<(BATCH * NTOK * KNN + 255) / 256, 256>>>(out);
}